// round 10
// baseline (speedup 1.0000x reference)
#include <cuda_runtime.h>
#include <cuda_bf16.h>
#include <cstdint>

#define BB 2
#define CIN 64
#define HIN 128
#define WIN 256
#define COUTN 64
#define KK 9
#define HO 128
#define WO 256
#define HWIN (HIN*WIN)
#define HWO (HO*WO)

// smem (bytes): double-buffered S (hi/lo) + double-buffered W (hi/lo) + desc
#define SMEM_SHI(buf) ((buf)*65536)
#define SMEM_SLO(buf) ((buf)*65536 + 32768)
#define SMEM_WH(buf)  (131072 + (buf)*16384)
#define SMEM_WL(buf)  (131072 + (buf)*16384 + 8192)
#define SMEM_DESC     163840
#define SMEM_BYTES    172032
#define OPITCH 264

// named barrier ids (0 reserved for __syncthreads)
#define BAR_FULL0  1
#define BAR_EMPTY0 3
#define BAR_CONS   5

__device__ float         g_xt[(size_t)BB*HIN*WIN*CIN];   // NHWC x
__device__ __nv_bfloat16 g_wh[KK*COUTN*CIN];             // [k][cout][c]
__device__ __nv_bfloat16 g_wl[KK*COUTN*CIN];

__device__ __forceinline__ uint32_t smem_u32(const void* p) {
    uint32_t a;
    asm("{ .reg .u64 t; cvta.to.shared.u64 t, %1; cvt.u32.u64 %0, t; }" : "=r"(a) : "l"(p));
    return a;
}
#define SWZ128(o) ((o) ^ (((o) >> 3) & 0x70))
#define BAR_SYNC(id, cnt)   asm volatile("bar.sync %0, %1;"   :: "r"(id), "r"(cnt) : "memory")
#define BAR_ARRIVE(id, cnt) asm volatile("bar.arrive %0, %1;" :: "r"(id), "r"(cnt) : "memory")

#define LDSM4(R, ADDR) \
    asm volatile("ldmatrix.sync.aligned.m8n8.x4.shared.b16 {%0,%1,%2,%3}, [%4];" \
        : "=r"((R)[0]), "=r"((R)[1]), "=r"((R)[2]), "=r"((R)[3]) : "r"(ADDR))
#define MMA16816(D, A, Bv) \
    asm volatile("mma.sync.aligned.m16n8k16.row.col.f32.bf16.bf16.f32 " \
        "{%0,%1,%2,%3}, {%4,%5,%6,%7}, {%8,%9}, {%0,%1,%2,%3};" \
        : "+f"((D)[0]), "+f"((D)[1]), "+f"((D)[2]), "+f"((D)[3]) \
        : "r"((A)[0]), "r"((A)[1]), "r"((A)[2]), "r"((A)[3]), "r"((Bv)[0]), "r"((Bv)[1]))

// ---------- fused prep ----------
__global__ __launch_bounds__(256)
void prep(const float* __restrict__ x, const float* __restrict__ w) {
    if (blockIdx.x < 2048) {
        __shared__ float t[CIN][33];
        const int bw = blockIdx.x & 7;
        const int h  = (blockIdx.x >> 3) & (HIN-1);
        const int b  = blockIdx.x >> 10;
        const int w0 = bw << 5;
        const int tw = threadIdx.x & 31, tc = threadIdx.x >> 5;
        const float* src = x + ((size_t)(b*CIN)*HIN + h)*WIN + w0 + tw;
        #pragma unroll
        for (int c = tc; c < CIN; c += 8) t[c][tw] = src[(size_t)c*HWIN];
        __syncthreads();
        const int c  = threadIdx.x & 63;
        const int wg = threadIdx.x >> 6;
        float* dst = g_xt + ((size_t)((b*HIN + h)*WIN) + w0)*CIN + c;
        #pragma unroll
        for (int i = 0; i < 8; i++) {
            int wl = (wg << 3) + i;
            dst[(size_t)wl*CIN] = t[c][wl];
        }
    } else {
        int i = (blockIdx.x - 2048) * 256 + threadIdx.x;   // [k][cout][c]
        if (i < KK*COUTN*CIN) {
            int k    = i / (COUTN*CIN);
            int rem  = i % (COUTN*CIN);
            int cout = rem >> 6;
            int c    = rem & 63;
            float v = w[cout*(CIN*KK) + c*KK + k];
            __nv_bfloat16 h = __float2bfloat16_rn(v);
            g_wh[i] = h;
            g_wl[i] = __float2bfloat16_rn(v - __bfloat162float(h));
        }
    }
}

// ---------- main kernel: warp-specialized producer/consumer ----------
__global__ __launch_bounds__(512, 1)
void dcn_main(const float* __restrict__ off, const float* __restrict__ bias,
              float* __restrict__ out)
{
    extern __shared__ char smem[];
    const uint32_t sb = smem_u32(smem);
    float* s_desc = (float*)(smem + SMEM_DESC);

    const int tid  = threadIdx.x;
    const int ho   = blockIdx.x & (HO-1);
    const int b    = blockIdx.x >> 7;
    const int warp = tid >> 5;
    const int lane = tid & 31;

    const float* offb = off + (size_t)b*(2*KK*HWO) + ho*WO;
    const float* xb   = g_xt + (size_t)b*(HIN*WIN*CIN);

    if (warp < 8) {
        // ================= PRODUCER =================
        const int wp   = warp;
        const int ptid = tid;                 // 0..255
        const int m    = lane & 15;
        const int hp   = lane >> 4;
        const float* xm = xb + (m << 2);

        for (int k = 0; k < KK; k++) {
            const int buf = k & 1;
            if (k >= 2) BAR_SYNC(BAR_EMPTY0 + buf, 512);

            // stage W(k)
            {
                const uint4* srcH = (const uint4*)(g_wh + k*(COUTN*CIN));
                const uint4* srcL = (const uint4*)(g_wl + k*(COUTN*CIN));
                #pragma unroll
                for (int u = ptid; u < 512; u += 256) {
                    uint32_t o = u << 4, so = SWZ128(o);
                    *(uint4*)(smem + SMEM_WH(buf) + so) = srcH[u];
                    *(uint4*)(smem + SMEM_WL(buf) + so) = srcL[u];
                }
            }

            // descriptor for own pixel (once per px)
            {
                const int p = (wp << 5) + lane;
                const int ki = k / 3, kj = k % 3;
                const float oy = __ldg(offb + (2*k  )*HWO + p);
                const float ox = __ldg(offb + (2*k+1)*HWO + p);
                const float py = (float)(ho - 1 + ki) + oy;
                const float px = (float)(p - 1 + kj) + ox;
                const float y0f = floorf(py), x0f = floorf(px);
                const float wy = py - y0f,   wx = px - x0f;
                const int y0 = (int)y0f, x0 = (int)x0f;
                const int y1 = y0 + 1,   x1 = x0 + 1;
                const float vy0 = (y0 >= 0 && y0 < HIN) ? 1.f : 0.f;
                const float vy1 = (y1 >= 0 && y1 < HIN) ? 1.f : 0.f;
                const float vx0 = (x0 >= 0 && x0 < WIN) ? 1.f : 0.f;
                const float vx1 = (x1 >= 0 && x1 < WIN) ? 1.f : 0.f;
                const int ya = min(max(y0, 0), HIN-1), yb = min(max(y1, 0), HIN-1);
                const int xa = min(max(x0, 0), WIN-1), xc = min(max(x1, 0), WIN-1);
                ((int4*)s_desc)[p*2] = make_int4(ya*WIN + xa, ya*WIN + xc,
                                                 yb*WIN + xa, yb*WIN + xc);
                ((float4*)s_desc)[p*2 + 1] =
                    make_float4((1.f-wy)*(1.f-wx)*vy0*vx0, (1.f-wy)*wx*vy0*vx1,
                                wy*(1.f-wx)*vy1*vx0,       wy*wx*vy1*vx1);
            }
            __syncwarp();

            // channel-dense gather -> bf16 hi/lo tiles
            {
                const uint32_t shi = SMEM_SHI(buf), slo = SMEM_SLO(buf);
                #pragma unroll 4
                for (int t = 0; t < 16; t++) {
                    const int p = (wp << 5) + (t << 1) + hp;
                    const int4   o  = ((const int4*)s_desc)[p << 1];
                    const float4 wv = ((const float4*)s_desc)[(p << 1) + 1];
                    const float4 v00 = __ldg((const float4*)(xm + (size_t)o.x*CIN));
                    const float4 v01 = __ldg((const float4*)(xm + (size_t)o.y*CIN));
                    const float4 v10 = __ldg((const float4*)(xm + (size_t)o.z*CIN));
                    const float4 v11 = __ldg((const float4*)(xm + (size_t)o.w*CIN));
                    float4 s;
                    s.x = wv.x*v00.x + wv.y*v01.x + wv.z*v10.x + wv.w*v11.x;
                    s.y = wv.x*v00.y + wv.y*v01.y + wv.z*v10.y + wv.w*v11.y;
                    s.z = wv.x*v00.z + wv.y*v01.z + wv.z*v10.z + wv.w*v11.z;
                    s.w = wv.x*v00.w + wv.y*v01.w + wv.z*v10.w + wv.w*v11.w;
                    __nv_bfloat162 h01 = __floats2bfloat162_rn(s.x, s.y);
                    __nv_bfloat162 h23 = __floats2bfloat162_rn(s.z, s.w);
                    __nv_bfloat162 l01 = __floats2bfloat162_rn(s.x - __bfloat162float(h01.x),
                                                               s.y - __bfloat162float(h01.y));
                    __nv_bfloat162 l23 = __floats2bfloat162_rn(s.z - __bfloat162float(h23.x),
                                                               s.w - __bfloat162float(h23.y));
                    uint32_t bo = (uint32_t)(p << 7) + (m << 3);
                    uint32_t so = SWZ128(bo);
                    *(uint2*)(smem + shi + so) = make_uint2(*(uint32_t*)&h01, *(uint32_t*)&h23);
                    *(uint2*)(smem + slo + so) = make_uint2(*(uint32_t*)&l01, *(uint32_t*)&l23);
                }
            }
            __threadfence_block();
            BAR_ARRIVE(BAR_FULL0 + buf, 512);
        }
    } else {
        // ================= CONSUMER =================
        const int wc = warp - 8;

        float acc[2][8][4];
        #pragma unroll
        for (int i = 0; i < 2; i++)
            #pragma unroll
            for (int j = 0; j < 8; j++)
                #pragma unroll
                for (int q = 0; q < 4; q++) acc[i][j][q] = 0.f;

        const int arow0 = (wc << 5) + (lane & 15);
        const uint32_t a_ch = (uint32_t)(lane >> 4) << 4;
        const int browp = ((lane >> 4) << 3) + (lane & 7);
        const uint32_t b_ch = (uint32_t)((lane >> 3) & 1) << 4;

        for (int k = 0; k < KK; k++) {
            const int buf = k & 1;
            BAR_SYNC(BAR_FULL0 + buf, 512);
            const uint32_t shi = SMEM_SHI(buf), slo = SMEM_SLO(buf);
            const uint32_t wh  = SMEM_WH(buf),  wl  = SMEM_WL(buf);

            #pragma unroll
            for (int kc = 0; kc < 4; kc++) {
                const uint32_t koff = (uint32_t)kc << 5;
                uint32_t ah[2][4], al[2][4];
                #pragma unroll
                for (int mt = 0; mt < 2; mt++) {
                    const int row = arow0 + (mt << 4);
                    const uint32_t addr = sb + (uint32_t)(row << 7)
                                        + ((koff + a_ch) ^ ((uint32_t)(row & 7) << 4));
                    LDSM4(ah[mt], addr + shi);
                    LDSM4(al[mt], addr + slo);
                }
                #pragma unroll
                for (int ntp = 0; ntp < 4; ntp++) {
                    const int row = (ntp << 4) + browp;
                    const uint32_t addr = sb + (uint32_t)(row << 7)
                                        + ((koff + b_ch) ^ ((uint32_t)(row & 7) << 4));
                    uint32_t bh[4], bl[4];
                    LDSM4(bh, addr + wh);
                    LDSM4(bl, addr + wl);
                    #pragma unroll
                    for (int mt = 0; mt < 2; mt++) {
                        MMA16816(acc[mt][2*ntp  ], ah[mt], bh    );
                        MMA16816(acc[mt][2*ntp  ], ah[mt], bl    );
                        MMA16816(acc[mt][2*ntp  ], al[mt], bh    );
                        MMA16816(acc[mt][2*ntp+1], ah[mt], bh + 2);
                        MMA16816(acc[mt][2*ntp+1], ah[mt], bl + 2);
                        MMA16816(acc[mt][2*ntp+1], al[mt], bh + 2);
                    }
                }
            }
            if (k <= KK - 3) BAR_ARRIVE(BAR_EMPTY0 + buf, 512);
        }

        // consumers-only barrier, then stage results into smem
        BAR_SYNC(BAR_CONS, 256);
        float* s_out = (float*)smem;          // [64 cout][OPITCH]
        #pragma unroll
        for (int nt = 0; nt < 8; nt++) {
            const int c0 = (nt << 3) + ((lane & 3) << 1);
            const float b0 = __ldg(bias + c0);
            const float b1 = __ldg(bias + c0 + 1);
            #pragma unroll
            for (int mt = 0; mt < 2; mt++) {
                const int px = (wc << 5) + (mt << 4) + (lane >> 2);
                s_out[ c0     *OPITCH + px    ] = acc[mt][nt][0] + b0;
                s_out[(c0 + 1)*OPITCH + px    ] = acc[mt][nt][1] + b1;
                s_out[ c0     *OPITCH + px + 8] = acc[mt][nt][2] + b0;
                s_out[(c0 + 1)*OPITCH + px + 8] = acc[mt][nt][3] + b1;
            }
        }
    }

    // all 512 threads: wait for staging, then coalesced stores
    __syncthreads();
    {
        const float* s_out = (const float*)smem;
        float* ob = out + (size_t)b*COUTN*HWO + ho*WO;
        #pragma unroll
        for (int r = 0; r < 8; r++) {
            const int idx = r*512 + tid;       // 4096 float4 slots
            const int c   = idx >> 6;
            const int q   = (idx & 63) << 2;
            *(float4*)(ob + (size_t)c*HWO + q) = *(const float4*)(s_out + c*OPITCH + q);
        }
    }
}

extern "C" void kernel_launch(void* const* d_in, const int* in_sizes, int n_in,
                              void* d_out, int out_size) {
    const float* x    = (const float*)d_in[0];
    const float* off  = (const float*)d_in[1];
    const float* w    = (const float*)d_in[2];
    const float* bias = (const float*)d_in[3];
    float* out = (float*)d_out;

    cudaFuncSetAttribute(dcn_main, cudaFuncAttributeMaxDynamicSharedMemorySize, SMEM_BYTES);

    prep<<<2048 + (KK*COUTN*CIN + 255)/256, 256>>>(x, w);
    dcn_main<<<BB*HO, 512, SMEM_BYTES>>>(off, bias, out);
}

// round 11
// speedup vs baseline: 1.2136x; 1.2136x over previous
#include <cuda_runtime.h>
#include <cuda_bf16.h>
#include <cstdint>

#define BB 2
#define CIN 64
#define HIN 128
#define WIN 256
#define COUTN 64
#define KK 9
#define HO 128
#define WO 256
#define HWIN (HIN*WIN)
#define HWO (HO*WO)

// smem layout (bytes):
// [0, 147456)        W table: 9 k * (hi 8KB + lo 8KB)   (reused as s_out in epilogue)
// [147456, 212992)   per-warp S: 16 warps * (hi 2KB + lo 2KB)
// [212992, 221184)   per-warp desc: 16 warps * 512 B
#define SMEM_WK(k)    ((k)*16384)
#define SMEM_S        147456
#define SMEM_DESC     212992
#define SMEM_BYTES    221184
#define OPITCH 264

__device__ float         g_xt[(size_t)BB*HIN*WIN*CIN];   // NHWC x
__device__ __nv_bfloat16 g_wh[KK*COUTN*CIN];             // [k][cout][c]
__device__ __nv_bfloat16 g_wl[KK*COUTN*CIN];

__device__ __forceinline__ uint32_t smem_u32(const void* p) {
    uint32_t a;
    asm("{ .reg .u64 t; cvta.to.shared.u64 t, %1; cvt.u32.u64 %0, t; }" : "=r"(a) : "l"(p));
    return a;
}
#define SWZ128(o) ((o) ^ (((o) >> 3) & 0x70))

#define LDSM4(R, ADDR) \
    asm volatile("ldmatrix.sync.aligned.m8n8.x4.shared.b16 {%0,%1,%2,%3}, [%4];" \
        : "=r"((R)[0]), "=r"((R)[1]), "=r"((R)[2]), "=r"((R)[3]) : "r"(ADDR))
#define MMA16816(D, A, Bv) \
    asm volatile("mma.sync.aligned.m16n8k16.row.col.f32.bf16.bf16.f32 " \
        "{%0,%1,%2,%3}, {%4,%5,%6,%7}, {%8,%9}, {%0,%1,%2,%3};" \
        : "+f"((D)[0]), "+f"((D)[1]), "+f"((D)[2]), "+f"((D)[3]) \
        : "r"((A)[0]), "r"((A)[1]), "r"((A)[2]), "r"((A)[3]), "r"((Bv)[0]), "r"((Bv)[1]))

// ---------- fused prep ----------
__global__ __launch_bounds__(256)
void prep(const float* __restrict__ x, const float* __restrict__ w) {
    if (blockIdx.x < 2048) {
        __shared__ float t[CIN][33];
        const int bw = blockIdx.x & 7;
        const int h  = (blockIdx.x >> 3) & (HIN-1);
        const int b  = blockIdx.x >> 10;
        const int w0 = bw << 5;
        const int tw = threadIdx.x & 31, tc = threadIdx.x >> 5;
        const float* src = x + ((size_t)(b*CIN)*HIN + h)*WIN + w0 + tw;
        #pragma unroll
        for (int c = tc; c < CIN; c += 8) t[c][tw] = src[(size_t)c*HWIN];
        __syncthreads();
        const int c  = threadIdx.x & 63;
        const int wg = threadIdx.x >> 6;
        float* dst = g_xt + ((size_t)((b*HIN + h)*WIN) + w0)*CIN + c;
        #pragma unroll
        for (int i = 0; i < 8; i++) {
            int wl = (wg << 3) + i;
            dst[(size_t)wl*CIN] = t[c][wl];
        }
    } else {
        int i = (blockIdx.x - 2048) * 256 + threadIdx.x;   // [k][cout][c]
        if (i < KK*COUTN*CIN) {
            int k    = i / (COUTN*CIN);
            int rem  = i % (COUTN*CIN);
            int cout = rem >> 6;
            int c    = rem & 63;
            float v = w[cout*(CIN*KK) + c*KK + k];
            __nv_bfloat16 h = __float2bfloat16_rn(v);
            g_wh[i] = h;
            g_wl[i] = __float2bfloat16_rn(v - __bfloat162float(h));
        }
    }
}

// ---------- main kernel: free-running warps, zero inner block barriers ----------
__global__ __launch_bounds__(512, 1)
void dcn_main(const float* __restrict__ off, const float* __restrict__ bias,
              float* __restrict__ out)
{
    extern __shared__ char smem[];
    const uint32_t sb = smem_u32(smem);

    const int tid  = threadIdx.x;
    const int ho   = blockIdx.x & (HO-1);
    const int b    = blockIdx.x >> 7;
    const int warp = tid >> 5;            // 16 warps, warp owns px [warp*16, warp*16+16)
    const int lane = tid & 31;
    const int m    = lane & 15;
    const int hp   = lane >> 4;

    const float* offb = off + (size_t)b*(2*KK*HWO) + ho*WO;
    const float* xb   = g_xt + (size_t)b*(HIN*WIN*CIN);
    const float* xm   = xb + (m << 2);

    // ---- prologue: stage full W table (all 9 k, hi+lo) ----
    {
        #pragma unroll
        for (int i = tid; i < 9216; i += 512) {           // uint4 slots
            const int k    = i >> 10;
            const int half = (i >> 9) & 1;
            const int u    = i & 511;
            const uint4 v  = half ? ((const uint4*)g_wl)[(k << 9) + u]
                                  : ((const uint4*)g_wh)[(k << 9) + u];
            const uint32_t doff = SMEM_WK(k) + (half << 13) + SWZ128((uint32_t)(u << 4));
            *(uint4*)(smem + doff) = v;
        }
    }
    __syncthreads();

    // per-warp regions
    const uint32_t wS    = SMEM_S    + ((uint32_t)warp << 12);   // hi 2KB, lo +2048
    float*         wDesc = (float*)(smem + SMEM_DESC + (warp << 9));

    float acc[8][4];
    #pragma unroll
    for (int j = 0; j < 8; j++)
        #pragma unroll
        for (int q = 0; q < 4; q++) acc[j][q] = 0.f;

    const int arow = lane & 15;                              // A row (local px)
    const uint32_t a_ch = (uint32_t)(lane >> 4) << 4;
    const int browp = ((lane >> 4) << 3) + (lane & 7);       // B rows for nt-pair x4
    const uint32_t b_ch = (uint32_t)((lane >> 3) & 1) << 4;
    const uint32_t a_swz = (uint32_t)(arow & 7) << 4;
    const uint32_t a_base = sb + wS + (uint32_t)(arow << 7);

    #pragma unroll 1
    for (int k = 0; k < KK; k++) {
        // ---- desc: lanes 0-15 compute their own pixel ----
        if (lane < 16) {
            const int p  = (warp << 4) + lane;
            const int ki = k / 3, kj = k % 3;
            const float oy = __ldg(offb + (2*k  )*HWO + p);
            const float ox = __ldg(offb + (2*k+1)*HWO + p);
            const float py = (float)(ho - 1 + ki) + oy;
            const float px = (float)(p - 1 + kj) + ox;
            const float y0f = floorf(py), x0f = floorf(px);
            const float wy = py - y0f,   wx = px - x0f;
            const int y0 = (int)y0f, x0 = (int)x0f;
            const int y1 = y0 + 1,   x1 = x0 + 1;
            const float vy0 = (y0 >= 0 && y0 < HIN) ? 1.f : 0.f;
            const float vy1 = (y1 >= 0 && y1 < HIN) ? 1.f : 0.f;
            const float vx0 = (x0 >= 0 && x0 < WIN) ? 1.f : 0.f;
            const float vx1 = (x1 >= 0 && x1 < WIN) ? 1.f : 0.f;
            const int ya = min(max(y0, 0), HIN-1), yb = min(max(y1, 0), HIN-1);
            const int xa = min(max(x0, 0), WIN-1), xc = min(max(x1, 0), WIN-1);
            ((int4*)wDesc)[lane*2] = make_int4(ya*WIN + xa, ya*WIN + xc,
                                               yb*WIN + xa, yb*WIN + xc);
            ((float4*)wDesc)[lane*2 + 1] =
                make_float4((1.f-wy)*(1.f-wx)*vy0*vx0, (1.f-wy)*wx*vy0*vx1,
                            wy*(1.f-wx)*vy1*vx0,       wy*wx*vy1*vx1);
        }
        __syncwarp();

        // ---- gather: 16 px x 64 ch -> bf16 hi/lo, warp-private tile ----
        #pragma unroll 4
        for (int t = 0; t < 8; t++) {
            const int pl = (t << 1) + hp;                    // local px
            const int4   o  = ((const int4*)wDesc)[pl << 1];
            const float4 wv = ((const float4*)wDesc)[(pl << 1) + 1];
            const float4 v00 = __ldg((const float4*)(xm + (size_t)o.x*CIN));
            const float4 v01 = __ldg((const float4*)(xm + (size_t)o.y*CIN));
            const float4 v10 = __ldg((const float4*)(xm + (size_t)o.z*CIN));
            const float4 v11 = __ldg((const float4*)(xm + (size_t)o.w*CIN));
            float4 s;
            s.x = wv.x*v00.x + wv.y*v01.x + wv.z*v10.x + wv.w*v11.x;
            s.y = wv.x*v00.y + wv.y*v01.y + wv.z*v10.y + wv.w*v11.y;
            s.z = wv.x*v00.z + wv.y*v01.z + wv.z*v10.z + wv.w*v11.z;
            s.w = wv.x*v00.w + wv.y*v01.w + wv.z*v10.w + wv.w*v11.w;
            __nv_bfloat162 h01 = __floats2bfloat162_rn(s.x, s.y);
            __nv_bfloat162 h23 = __floats2bfloat162_rn(s.z, s.w);
            __nv_bfloat162 l01 = __floats2bfloat162_rn(s.x - __bfloat162float(h01.x),
                                                       s.y - __bfloat162float(h01.y));
            __nv_bfloat162 l23 = __floats2bfloat162_rn(s.z - __bfloat162float(h23.x),
                                                       s.w - __bfloat162float(h23.y));
            const uint32_t so = SWZ128((uint32_t)(pl << 7) + (m << 3));
            *(uint2*)(smem + wS + so)        = make_uint2(*(uint32_t*)&h01, *(uint32_t*)&h23);
            *(uint2*)(smem + wS + 2048 + so) = make_uint2(*(uint32_t*)&l01, *(uint32_t*)&l23);
        }
        __syncwarp();

        // ---- GEMM: A from warp-private S, B from shared W[k] ----
        const uint32_t wkb = sb + SMEM_WK(k);
        #pragma unroll
        for (int kc = 0; kc < 4; kc++) {
            const uint32_t koff = (uint32_t)kc << 5;
            uint32_t ah[4], al[4];
            {
                const uint32_t addr = a_base + ((koff + a_ch) ^ a_swz);
                LDSM4(ah, addr);
                LDSM4(al, addr + 2048);
            }
            #pragma unroll
            for (int ntp = 0; ntp < 4; ntp++) {
                const int row = (ntp << 4) + browp;
                const uint32_t addr = wkb + (uint32_t)(row << 7)
                                    + ((koff + b_ch) ^ ((uint32_t)(row & 7) << 4));
                uint32_t bh[4], bl[4];
                LDSM4(bh, addr);
                LDSM4(bl, addr + 8192);
                MMA16816(acc[2*ntp  ], ah, bh    );
                MMA16816(acc[2*ntp  ], ah, bl    );
                MMA16816(acc[2*ntp  ], al, bh    );
                MMA16816(acc[2*ntp+1], ah, bh + 2);
                MMA16816(acc[2*ntp+1], ah, bl + 2);
                MMA16816(acc[2*ntp+1], al, bh + 2);
            }
        }
        __syncwarp();   // LDSM reads of warp S done before next k's STS
    }

    // ---- epilogue: reuse W area as [64 cout][OPITCH] staging ----
    __syncthreads();
    float* s_out = (float*)smem;
    #pragma unroll
    for (int nt = 0; nt < 8; nt++) {
        const int c0 = (nt << 3) + ((lane & 3) << 1);
        const float b0 = __ldg(bias + c0);
        const float b1 = __ldg(bias + c0 + 1);
        const int px = (warp << 4) + (lane >> 2);
        s_out[ c0     *OPITCH + px    ] = acc[nt][0] + b0;
        s_out[(c0 + 1)*OPITCH + px    ] = acc[nt][1] + b1;
        s_out[ c0     *OPITCH + px + 8] = acc[nt][2] + b0;
        s_out[(c0 + 1)*OPITCH + px + 8] = acc[nt][3] + b1;
    }
    __syncthreads();
    {
        float* ob = out + (size_t)b*COUTN*HWO + ho*WO;
        #pragma unroll
        for (int r = 0; r < 8; r++) {
            const int idx = r*512 + tid;       // 4096 float4 slots
            const int c   = idx >> 6;
            const int q   = (idx & 63) << 2;
            *(float4*)(ob + (size_t)c*HWO + q) = *(const float4*)(s_out + c*OPITCH + q);
        }
    }
}

extern "C" void kernel_launch(void* const* d_in, const int* in_sizes, int n_in,
                              void* d_out, int out_size) {
    const float* x    = (const float*)d_in[0];
    const float* off  = (const float*)d_in[1];
    const float* w    = (const float*)d_in[2];
    const float* bias = (const float*)d_in[3];
    float* out = (float*)d_out;

    cudaFuncSetAttribute(dcn_main, cudaFuncAttributeMaxDynamicSharedMemorySize, SMEM_BYTES);

    prep<<<2048 + (KK*COUTN*CIN + 255)/256, 256>>>(x, w);
    dcn_main<<<BB*HO, 512, SMEM_BYTES>>>(off, bias, out);
}